// round 16
// baseline (speedup 1.0000x reference)
#include <cuda_runtime.h>
#include <cuda_fp16.h>

#define BSZ   2048
#define TENC  32
#define DIN   512
#define HDIM  256
#define NCLS  38
#define STEPS 26   // MAXLEN+1
#define NHP   320  // hp(256) + probs(38) padded to 320
#define RS    20   // padded smem row stride in 32-bit words
#define HS2   132  // fused-attn h-tile row stride (words)
#define BSR   12   // fused-attn B-slice row stride (words)

// ---------------- scratch (device globals: allocation-free) ----------------
__device__ __align__(16) __half2 g_HprojH[(size_t)BSZ * TENC * HDIM / 2];  // 32 MB fp16
__device__ __align__(16) __half2 g_bhH[(size_t)BSZ * TENC * DIN / 2];      // 64 MB fp16
__device__ __align__(16) float    g_hp[BSZ * HDIM];                        // tail scratch
__device__ __align__(16) unsigned g_ctxH[BSZ * DIN / 2];                   // fp16 pairs
__device__ __align__(16) unsigned g_hH[2][BSZ * HDIM / 2];                 // fp16 pairs
__device__ __align__(16) float    g_c[BSZ * HDIM];
// packed fp16 B matrices (row = output col, K contiguous, 2 fp16 per word)
__device__ __align__(16) unsigned g_BpG[4 * HDIM * (DIN + HDIM) / 2];
__device__ __align__(16) unsigned g_BpH[NHP * HDIM / 2];
__device__ __align__(16) unsigned g_BpHT[16 * NHP * 8];  // k-major slices: [kk][n][8]
__device__ __align__(16) unsigned g_BpI[HDIM * DIN / 2];
__device__ __align__(16) float    g_biasG[4 * HDIM];

// ---------------- helpers ----------------
__device__ __forceinline__ unsigned pack_h2(float a, float b) {
    __half2 h = __floats2half2_rn(a, b);
    return *reinterpret_cast<unsigned*>(&h);
}
__device__ __forceinline__ float tanha(float x) {
    float y;
    asm("tanh.approx.f32 %0, %1;" : "=f"(y) : "f"(x));
    return y;
}
__device__ __forceinline__ void mma_f16(float* c, const unsigned* a, const unsigned* b) {
    asm volatile(
        "mma.sync.aligned.m16n8k16.row.col.f32.f16.f16.f32 "
        "{%0,%1,%2,%3},{%4,%5,%6,%7},{%8,%9},{%0,%1,%2,%3};"
        : "+f"(c[0]), "+f"(c[1]), "+f"(c[2]), "+f"(c[3])
        : "r"(a[0]), "r"(a[1]), "r"(a[2]), "r"(a[3]), "r"(b[0]), "r"(b[1]));
}
__device__ __forceinline__ void ldsm4(unsigned* r, unsigned addr) {
    asm volatile("ldmatrix.sync.aligned.m8n8.x4.shared.b16 {%0,%1,%2,%3}, [%4];"
                 : "=r"(r[0]), "=r"(r[1]), "=r"(r[2]), "=r"(r[3]) : "r"(addr));
}
__device__ __forceinline__ void cp16(unsigned saddr, const void* gptr) {
    asm volatile("cp.async.cg.shared.global [%0], [%1], 16;" :: "r"(saddr), "l"(gptr));
}
__device__ __forceinline__ void cp_commit() {
    asm volatile("cp.async.commit_group;" ::: "memory");
}
__device__ __forceinline__ void cp_wait1() {
    asm volatile("cp.async.wait_group 1;" ::: "memory");
}
__device__ __forceinline__ void cp_wait0() {
    asm volatile("cp.async.wait_group 0;" ::: "memory");
}

// ---------------- init: zero LSTM state, hp = b_h2h ----------------
__global__ void init_kernel(const float* __restrict__ b_h2h) {
    int i = blockIdx.x * blockDim.x + threadIdx.x;
    if (i < BSZ * HDIM) { g_c[i] = 0.f; g_hp[i] = b_h2h[i & (HDIM - 1)]; }
    if (i < BSZ * HDIM / 2) g_hH[0][i] = 0u;
}

// ---------------- convert batch_H -> fp16 (one-time) ----------------
__global__ void cvt_bh_kernel(const float4* __restrict__ in) {
    size_t i = (size_t)blockIdx.x * 256 + threadIdx.x;   // < 8M
    float4 v = in[i];
    g_bhH[2 * i]     = __float22half2_rn(make_float2(v.x, v.y));
    g_bhH[2 * i + 1] = __float22half2_rn(make_float2(v.z, v.w));
}

// ---------------- pack weights to fp16 pairs ----------------
__global__ void pack_kernel(
    const float* __restrict__ W_ih, const float* __restrict__ W_hh,
    const float* __restrict__ W_h2h, const float* __restrict__ W_gen,
    const float* __restrict__ W_i2h,
    const float* __restrict__ b_ih, const float* __restrict__ b_hh)
{
    const int NG2 = 4 * HDIM * (DIN + HDIM) / 2;   // 393216
    const int NH2 = NHP * HDIM / 2;                // 40960
    const int NT2 = 16 * NHP * 8;                  // 40960
    const int NI2 = HDIM * DIN / 2;                // 65536
    int i = blockIdx.x * blockDim.x + threadIdx.x;
    if (i < NG2) {
        int p = i / 384, k = (i % 384) * 2;
        int blk = p >> 7, q = p & 127;
        int wn = q >> 5, gate = (q >> 3) & 3, uu = q & 7;
        int n = gate * 256 + blk * 32 + wn * 8 + uu;
        float v0, v1;
        if (k < DIN) {
            v0 = W_ih[(size_t)n * (DIN + NCLS) + k];
            v1 = W_ih[(size_t)n * (DIN + NCLS) + k + 1];
        } else {
            v0 = W_hh[(size_t)n * HDIM + (k - DIN)];
            v1 = W_hh[(size_t)n * HDIM + (k - DIN) + 1];
        }
        g_BpG[i] = pack_h2(v0, v1);
    } else if (i < NG2 + NH2 + NT2) {
        // BpH (row-major) and BpHT (k-major slices) share the value logic
        int j = i - NG2;
        int n, kw;
        bool toT = (j >= NH2);
        if (!toT) { n = j / 128; kw = j % 128; }
        else {
            int jj = j - NH2;
            int kk = jj / (NHP * 8), rem = jj % (NHP * 8);
            n = rem >> 3; kw = kk * 8 + (rem & 7);
        }
        int k = kw * 2;
        float v0 = 0.f, v1 = 0.f;
        if (n < HDIM) {
            v0 = W_h2h[(size_t)n * HDIM + k];
            v1 = W_h2h[(size_t)n * HDIM + k + 1];
        } else if (n < HDIM + NCLS) {
            v0 = W_gen[(size_t)(n - HDIM) * HDIM + k];
            v1 = W_gen[(size_t)(n - HDIM) * HDIM + k + 1];
        }
        if (!toT) g_BpH[j] = pack_h2(v0, v1);
        else      g_BpHT[j - NH2] = pack_h2(v0, v1);
    } else if (i < NG2 + NH2 + NT2 + NI2) {
        int j = i - NG2 - NH2 - NT2;
        g_BpI[j] = pack_h2(W_i2h[2 * j], W_i2h[2 * j + 1]);
    } else if (i < NG2 + NH2 + NT2 + NI2 + 4 * HDIM) {
        int j = i - NG2 - NH2 - NT2 - NI2;
        g_biasG[j] = b_ih[j] + b_hh[j];
    }
}

// ---------------- pipelined fp16 GEMM (H_proj / gates / tail probs) --------
template <int EPI, int NW, int MT>
__global__ void __launch_bounds__(64 * NW) gemm_f16(
    const unsigned* __restrict__ A0, int lda0,
    const unsigned* __restrict__ A1, int lda1, int KA,
    const unsigned* __restrict__ Bp, int ldb,
    float* __restrict__ C, int ldc, int K, int yoff,
    const float* __restrict__ bias0, const float* __restrict__ bias1,
    const float* __restrict__ Wih, const int* __restrict__ text,
    float* __restrict__ out2, unsigned* __restrict__ ohw, int step)
{
    constexpr int T  = 64 * NW;
    constexpr int BM = 32 * MT;
    constexpr int BN = 32 * NW;
    constexpr int AN = (2 * MT) / NW ? (2 * MT) / NW : 1;
    extern __shared__ unsigned sh[];
    unsigned* AsP = sh;
    unsigned* BsP = sh + 3 * BM * RS;
    const unsigned ABYTES = BM * RS * 4;
    const unsigned BBYTES = BN * RS * 4;

    const int tid  = threadIdx.x;
    const int lane = tid & 31;
    const int warp = tid >> 5;
    const int wm   = warp & 1;
    const int wn   = warp >> 1;
    const int g    = lane >> 2;
    const int ctg  = lane & 3;
    const int mBase = blockIdx.x * BM;
    const int nBase = (blockIdx.y + yoff) * BN;

    float acc[MT][4][4];
#pragma unroll
    for (int mt = 0; mt < MT; mt++)
#pragma unroll
        for (int nt = 0; nt < 4; nt++)
#pragma unroll
            for (int i = 0; i < 4; i++) acc[mt][nt][i] = 0.f;

    const int nk = K >> 5;

    const unsigned asBase = (unsigned)__cvta_generic_to_shared(AsP);
    const unsigned bsBase = (unsigned)__cvta_generic_to_shared(BsP);
    const int aRowL = wm * (MT * 16) + (lane & 7) + ((lane >> 3) & 1) * 8;
    const int aColL = (lane >> 4) * 4;
    const unsigned aAddr0 = asBase + (aRowL * RS + aColL) * 4;
    const int bRowL = wn * 32 + (lane >> 4) * 8 + (lane & 7);
    const int bColL = ((lane >> 3) & 1) * 4;
    const unsigned bAddr0 = bsBase + (bRowL * RS + bColL) * 4;

    auto cpasync_tile = [&](int kt, int st) {
        const int k0 = kt << 5;
        const unsigned* aS; int aLd, aOffW;
        if (k0 < KA) { aS = A0; aLd = lda0; aOffW = k0 >> 1; }
        else         { aS = A1; aLd = lda1; aOffW = (k0 - KA) >> 1; }
        const unsigned aDst = asBase + st * ABYTES;
        const unsigned bDst = bsBase + st * BBYTES;
#pragma unroll
        for (int t = 0; t < AN; t++) {
            int i = t * T + tid;
            int r = i >> 2, cg = i & 3;
            cp16(aDst + (r * RS + cg * 4) * 4,
                 aS + (size_t)(mBase + r) * aLd + aOffW + cg * 4);
        }
#pragma unroll
        for (int t = 0; t < 2; t++) {
            int i = t * T + tid;
            int r = i >> 2, cg = i & 3;
            cp16(bDst + (r * RS + cg * 4) * 4,
                 Bp + (size_t)(nBase + r) * ldb + (k0 >> 1) + cg * 4);
        }
    };

    cpasync_tile(0, 0);
    cp_commit();
    if (nk > 1) { cpasync_tile(1, 1); cp_commit(); }

    int cur = 0;
    for (int kt = 0; kt < nk; kt++) {
        if (kt + 1 < nk) cp_wait1(); else cp_wait0();
        __syncthreads();

        if (kt + 2 < nk) {
            int pf = cur + 2; if (pf >= 3) pf -= 3;
            cpasync_tile(kt + 2, pf);
            cp_commit();
        }

        const unsigned bufA = cur * ABYTES;
        const unsigned bufB = cur * BBYTES;
#pragma unroll
        for (int kk = 0; kk < 2; kk++) {
            unsigned af[MT][4], bf[2][4];
#pragma unroll
            for (int mt = 0; mt < MT; mt++)
                ldsm4(af[mt], aAddr0 + bufA + (unsigned)(mt * 16 * RS * 4 + kk * 32));
#pragma unroll
            for (int p = 0; p < 2; p++)
                ldsm4(bf[p], bAddr0 + bufB + (unsigned)(p * 16 * RS * 4 + kk * 32));
#pragma unroll
            for (int mt = 0; mt < MT; mt++)
#pragma unroll
                for (int nt = 0; nt < 4; nt++)
                    mma_f16(acc[mt][nt], af[mt], &bf[nt >> 1][(nt & 1) * 2]);
        }

        cur = (cur == 2) ? 0 : cur + 1;
    }

    const int unit0 = blockIdx.y * 32 + wn * 8 + 2 * ctg;  // EPI 2 only
#pragma unroll
    for (int mt = 0; mt < MT; mt++) {
        int r0 = mBase + wm * (MT * 16) + mt * 16 + g;
        int r1 = r0 + 8;
        if (EPI == 0) {
#pragma unroll
            for (int nt = 0; nt < 4; nt++) {
                int c0 = nBase + wn * 32 + nt * 8 + 2 * ctg;
                ohw[((size_t)r0 * ldc + c0) >> 1] = pack_h2(acc[mt][nt][0], acc[mt][nt][1]);
                ohw[((size_t)r1 * ldc + c0) >> 1] = pack_h2(acc[mt][nt][2], acc[mt][nt][3]);
            }
        } else if (EPI == 1) {
#pragma unroll
            for (int nt = 0; nt < 4; nt++) {
                int c0 = nBase + wn * 32 + nt * 8 + 2 * ctg;
                if (c0 < HDIM) {
                    float b0 = bias0[c0], b1 = bias0[c0 + 1];
                    *reinterpret_cast<float2*>(C + (size_t)r0 * ldc + c0) =
                        make_float2(acc[mt][nt][0] + b0, acc[mt][nt][1] + b1);
                    *reinterpret_cast<float2*>(C + (size_t)r1 * ldc + c0) =
                        make_float2(acc[mt][nt][2] + b0, acc[mt][nt][3] + b1);
                } else if (c0 < HDIM + NCLS) {
                    int cc = c0 - HDIM;
                    float b0 = bias1[cc], b1 = bias1[cc + 1];
                    *reinterpret_cast<float2*>(
                        out2 + (size_t)r0 * (STEPS * NCLS) + step * NCLS + cc) =
                        make_float2(acc[mt][nt][0] + b0, acc[mt][nt][1] + b1);
                    *reinterpret_cast<float2*>(
                        out2 + (size_t)r1 * (STEPS * NCLS) + step * NCLS + cc) =
                        make_float2(acc[mt][nt][2] + b0, acc[mt][nt][3] + b1);
                }
            }
        } else {  // EPI == 2: fused LSTM (nt == gate)
            int chr0 = text[r0 * STEPS + step];
            int chr1 = text[r1 * STEPS + step];
            float gv0[4][2], gv1[4][2];
#pragma unroll
            for (int gate = 0; gate < 4; gate++) {
                int n0 = gate * 256 + unit0;
                float b0 = g_biasG[n0], b1 = g_biasG[n0 + 1];
                const float* w0 = Wih + (size_t)n0 * 550 + 512;
                const float* w1 = w0 + 550;
                gv0[gate][0] = acc[mt][gate][0] + b0 + w0[chr0];
                gv0[gate][1] = acc[mt][gate][1] + b1 + w1[chr0];
                gv1[gate][0] = acc[mt][gate][2] + b0 + w0[chr1];
                gv1[gate][1] = acc[mt][gate][3] + b1 + w1[chr1];
            }
            auto cell = [](float i_, float f_, float g_, float o_, float c_,
                           float& cn, float& hn) {
                float si = 1.f / (1.f + __expf(-i_));
                float sf = 1.f / (1.f + __expf(-f_));
                float so = 1.f / (1.f + __expf(-o_));
                cn = sf * c_ + si * tanhf(g_);
                hn = so * tanhf(cn);
            };
            float2 cold0 = *reinterpret_cast<float2*>(g_c + r0 * HDIM + unit0);
            float2 cold1 = *reinterpret_cast<float2*>(g_c + r1 * HDIM + unit0);
            float2 cn0, hn0, cn1, hn1;
            cell(gv0[0][0], gv0[1][0], gv0[2][0], gv0[3][0], cold0.x, cn0.x, hn0.x);
            cell(gv0[0][1], gv0[1][1], gv0[2][1], gv0[3][1], cold0.y, cn0.y, hn0.y);
            cell(gv1[0][0], gv1[1][0], gv1[2][0], gv1[3][0], cold1.x, cn1.x, hn1.x);
            cell(gv1[0][1], gv1[1][1], gv1[2][1], gv1[3][1], cold1.y, cn1.y, hn1.y);
            *reinterpret_cast<float2*>(g_c + r0 * HDIM + unit0) = cn0;
            *reinterpret_cast<float2*>(g_c + r1 * HDIM + unit0) = cn1;
            ohw[(r0 * HDIM + unit0) >> 1] = pack_h2(hn0.x, hn0.y);
            ohw[(r1 * HDIM + unit0) >> 1] = pack_h2(hn1.x, hn1.y);
        }
    }
}

// ---------------- fused: hp MMA + probs(step-1) + attention ----------------
// 256 blocks x 256 threads; block owns 8 batches.
// Phase 1: hp[8,256] = h @ W_h2h^T (+b), probs via W_gen cols (bit-identical
//          to old hp GEMM: same 16 ascending k16 MMAs). B streamed from
//          k-major g_BpHT via coalesced cp.async 2-stage ring.
// Phase 2: scores/softmax/ctx — identical instruction order to old attn.
__global__ void __launch_bounds__(256) fused_attn(
    const unsigned* __restrict__ hR,
    const float* __restrict__ b_h2h, const float* __restrict__ b_gen,
    const float* __restrict__ Wscore, float* __restrict__ out, int step)
{
    extern __shared__ unsigned sh[];
    unsigned* hs   = sh;                          // 16*HS2 words
    unsigned* Bst  = sh + 16 * HS2;               // 2 * 344*BSR words
    float*    hp_s = (float*)(Bst + 2 * 344 * BSR); // 8*256 floats
    float*    w_s  = hp_s + 8 * 256;              // 256
    float*    e_s  = w_s + 256;                   // 256

    const int tid  = threadIdx.x;
    const int lane = tid & 31;
    const int w    = tid >> 5;
    const int b0   = blockIdx.x * 8;

    // load h tile (8 rows x 128 words) + zero rows 8..15
#pragma unroll
    for (int t = 0; t < 4; t++) {
        int i = t * 256 + tid;
        int r = i >> 7, q = i & 127;
        hs[r * HS2 + q] = hR[(size_t)(b0 + r) * 128 + q];
        hs[(r + 8) * HS2 + q] = 0u;
    }
    w_s[tid] = Wscore[tid];

    const unsigned hsBase  = (unsigned)__cvta_generic_to_shared(hs);
    const unsigned bstBase = (unsigned)__cvta_generic_to_shared(Bst);
    const unsigned BSZB = 344 * BSR * 4;

    // B slice cp.async: slice kk = g_BpHT[kk*2560 .. +2560) -> 320 rows x 8 w
    auto cpB = [&](int kk, int st) {
        const unsigned dst = bstBase + st * BSZB;
        const unsigned* src = g_BpHT + kk * (NHP * 8);
#pragma unroll
        for (int t = 0; t < 3; t++) {
            int i = t * 256 + tid;
            if (i < 640) {
                int n = i >> 1, half = i & 1;
                cp16(dst + (n * BSR + half * 4) * 4, src + n * 8 + half * 4);
            }
        }
    };

    cpB(0, 0); cp_commit();
    cpB(1, 1); cp_commit();
    cp_wait1();
    __syncthreads();   // hs + slice0 ready

    // ---- phase 1: hp MMA ----
    const int g   = lane >> 2;
    const int ctg = lane & 3;
    const int n0  = w * 40;
    const unsigned aAddr0 = hsBase +
        (((lane & 7) + ((lane >> 3) & 1) * 8) * HS2) * 4 + (lane >> 4) * 16;
    const unsigned bAddr0 = bstBase +
        ((n0 + (lane >> 4) * 8 + (lane & 7)) * BSR + ((lane >> 3) & 1) * 4) * 4;

    float acc5[5][4];
#pragma unroll
    for (int j = 0; j < 5; j++)
#pragma unroll
        for (int i = 0; i < 4; i++) acc5[j][i] = 0.f;

    for (int kk = 0; kk < 16; kk++) {
        const unsigned stOff = (kk & 1) * BSZB;
        unsigned af[4];
        ldsm4(af, aAddr0 + kk * 32);
        unsigned bf[3][4];
#pragma unroll
        for (int p = 0; p < 3; p++)
            ldsm4(bf[p], bAddr0 + stOff + (unsigned)(p * 16 * BSR * 4));
#pragma unroll
        for (int j = 0; j < 5; j++)
            mma_f16(acc5[j], af, &bf[j >> 1][(j & 1) * 2]);

        __syncthreads();
        if (kk + 2 < 16) {
            cpB(kk + 2, kk & 1);
            cp_commit();
            cp_wait1();
        } else if (kk + 1 < 16) {
            cp_wait0();
        }
        __syncthreads();
    }

#pragma unroll
    for (int j = 0; j < 5; j++) {
        int c0 = n0 + j * 8 + 2 * ctg;
        if (c0 < HDIM) {
            hp_s[g * 256 + c0]     = acc5[j][0] + b_h2h[c0];
            hp_s[g * 256 + c0 + 1] = acc5[j][1] + b_h2h[c0 + 1];
        } else if (c0 < HDIM + NCLS && step > 0) {
            int cc = c0 - HDIM;
            *reinterpret_cast<float2*>(
                out + (size_t)(b0 + g) * (STEPS * NCLS) + (step - 1) * NCLS + cc) =
                make_float2(acc5[j][0] + b_gen[cc], acc5[j][1] + b_gen[cc + 1]);
        }
    }
    __syncthreads();

    // ---- phase 2a: scores (warp w = batch w; same order as old attn) ----
    {
        const __half2* row0 = g_HprojH + ((size_t)(b0 + w) * TENC) * (HDIM / 2);
        const float* hpr = hp_s + w * 256;
#pragma unroll 4
        for (int t = 0; t < TENC; t++) {
            const __half2* row = row0 + t * (HDIM / 2);
            float s = 0.f;
#pragma unroll
            for (int j = 0; j < 4; j++) {
                int idx = lane + 32 * j;
                float2 r = __half22float2(row[idx]);
                float hh0 = hpr[2 * idx], hh1 = hpr[2 * idx + 1];
                float ww0 = w_s[2 * idx], ww1 = w_s[2 * idx + 1];
                s += ww0 * tanha(r.x + hh0) + ww1 * tanha(r.y + hh1);
            }
#pragma unroll
            for (int o = 16; o; o >>= 1) s += __shfl_xor_sync(0xffffffffu, s, o);
            if (lane == 0) e_s[w * 32 + t] = s;
        }
    }
    __syncthreads();

    // ---- phase 2b: softmax (warp w = batch w; shfl tree like old attn) ----
    {
        float v = e_s[w * 32 + lane];
        float m = v;
#pragma unroll
        for (int o = 16; o; o >>= 1) m = fmaxf(m, __shfl_xor_sync(0xffffffffu, m, o));
        float p = __expf(v - m);
        float ss = p;
#pragma unroll
        for (int o = 16; o; o >>= 1) ss += __shfl_xor_sync(0xffffffffu, ss, o);
        e_s[w * 32 + lane] = p / ss;
    }
    __syncthreads();

    // ---- phase 2c: ctx (thread = (batch w, lane): 8 words = 16 floats) ----
    {
        float ax[16];
#pragma unroll
        for (int i = 0; i < 16; i++) ax[i] = 0.f;
        const __half2* bh = g_bhH + ((size_t)(b0 + w) * TENC) * 256 + lane * 8;
#pragma unroll 4
        for (int t = 0; t < TENC; t++) {
            float al = e_s[w * 32 + t];
            const uint4* p = reinterpret_cast<const uint4*>(bh + t * 256);
#pragma unroll
            for (int q = 0; q < 2; q++) {
                uint4 v = p[q];
                float2 f0 = __half22float2(*reinterpret_cast<__half2*>(&v.x));
                float2 f1 = __half22float2(*reinterpret_cast<__half2*>(&v.y));
                float2 f2 = __half22float2(*reinterpret_cast<__half2*>(&v.z));
                float2 f3 = __half22float2(*reinterpret_cast<__half2*>(&v.w));
                ax[q * 8 + 0] += al * f0.x; ax[q * 8 + 1] += al * f0.y;
                ax[q * 8 + 2] += al * f1.x; ax[q * 8 + 3] += al * f1.y;
                ax[q * 8 + 4] += al * f2.x; ax[q * 8 + 5] += al * f2.y;
                ax[q * 8 + 6] += al * f3.x; ax[q * 8 + 7] += al * f3.y;
            }
        }
        unsigned* co = g_ctxH + (size_t)(b0 + w) * 256 + lane * 8;
#pragma unroll
        for (int k = 0; k < 8; k++) co[k] = pack_h2(ax[2 * k], ax[2 * k + 1]);
    }
}

// ---------------- launch ----------------
extern "C" void kernel_launch(void* const* d_in, const int* in_sizes, int n_in,
                              void* d_out, int out_size)
{
    const float* batchH  = (const float*)d_in[0];
    const int*   text    = (const int*)d_in[1];
    const float* W_i2h   = (const float*)d_in[2];
    const float* W_h2h   = (const float*)d_in[3];
    const float* b_h2h   = (const float*)d_in[4];
    const float* W_score = (const float*)d_in[5];
    const float* W_ih    = (const float*)d_in[6];
    const float* b_ih    = (const float*)d_in[7];
    const float* W_hh    = (const float*)d_in[8];
    const float* b_hh    = (const float*)d_in[9];
    const float* W_gen   = (const float*)d_in[10];
    const float* b_gen   = (const float*)d_in[11];
    float*       out     = (float*)d_out;

    float *hp;
    unsigned *ctxH, *h0, *h1, *bpG, *bpH, *bpI, *hprojW, *bhW;
    cudaGetSymbolAddress((void**)&hprojW, g_HprojH);
    cudaGetSymbolAddress((void**)&bhW,    g_bhH);
    cudaGetSymbolAddress((void**)&hp,     g_hp);
    cudaGetSymbolAddress((void**)&ctxH,   g_ctxH);
    cudaGetSymbolAddress((void**)&h0,     g_hH);
    h1 = h0 + BSZ * HDIM / 2;
    cudaGetSymbolAddress((void**)&bpG,    g_BpG);
    cudaGetSymbolAddress((void**)&bpH,    g_BpH);
    cudaGetSymbolAddress((void**)&bpI,    g_BpI);

    const int SM44 = 3 * (128 * RS + 128 * RS) * 4;  // H_proj: 61440 B
    const int SM42 = 3 * (64 * RS + 128 * RS) * 4;   // gates:  46080 B
    const int SM22 = 3 * (64 * RS + 64 * RS) * 4;    // tail:   30720 B
    const int SMFA = (16 * HS2 + 2 * 344 * BSR + 8 * 256 + 256 + 256) * 4; // 51712 B
    static int configured = 0;
    if (!configured) {
        cudaFuncSetAttribute((const void*)gemm_f16<0, 4, 4>,
                             cudaFuncAttributeMaxDynamicSharedMemorySize, SM44);
        cudaFuncSetAttribute((const void*)gemm_f16<2, 4, 2>,
                             cudaFuncAttributeMaxDynamicSharedMemorySize, SM42);
        cudaFuncSetAttribute((const void*)gemm_f16<1, 2, 2>,
                             cudaFuncAttributeMaxDynamicSharedMemorySize, SM22);
        cudaFuncSetAttribute((const void*)fused_attn,
                             cudaFuncAttributeMaxDynamicSharedMemorySize, SMFA);
        configured = 1;
    }

    init_kernel<<<(BSZ * HDIM) / 256, 256>>>(b_h2h);
    const int packN = 4 * HDIM * (DIN + HDIM) / 2 + NHP * HDIM / 2
                    + 16 * NHP * 8 + HDIM * DIN / 2 + 4 * HDIM;
    pack_kernel<<<(packN + 255) / 256, 256>>>(W_ih, W_hh, W_h2h, W_gen, W_i2h, b_ih, b_hh);
    cvt_bh_kernel<<<(BSZ * TENC * DIN / 4) / 256, 256>>>((const float4*)batchH);

    // H_proj (fp16 in/out): M=65536, N=256, K=512; BM=128, BN=128 -> (512,2)
    gemm_f16<0, 4, 4><<<dim3(512, 2), 256, SM44>>>(
        bhW, DIN / 2, nullptr, 0, DIN,
        bpI, DIN / 2,
        nullptr, HDIM, DIN, 0,
        nullptr, nullptr, nullptr, nullptr, nullptr, hprojW, 0);

    for (int s = 0; s < STEPS; s++) {
        unsigned* hR = (s & 1) ? h1 : h0;
        unsigned* hW = (s & 1) ? h0 : h1;
        // fused: hp(s) + probs(s-1) + attention -> ctx
        fused_attn<<<BSZ / 8, 256, SMFA>>>(hR, b_h2h, b_gen, W_score, out, s);
        // gates + fused LSTM: [ctx|h] @ BpG^T ; BM=64, BN=128 -> grid (32,8)
        gemm_f16<2, 4, 2><<<dim3(32, 8), 256, SM42>>>(
            ctxH, DIN / 2, hR, HDIM / 2, DIN,
            bpG, (DIN + HDIM) / 2,
            nullptr, 0, DIN + HDIM, 0,
            nullptr, nullptr, W_ih, text, nullptr, hW, s);
    }
    // probs for the final step (step 25 wrote h0)
    gemm_f16<1, 2, 2><<<dim3(32, 1), 128, SM22>>>(
        h0, HDIM / 2, nullptr, 0, HDIM,
        bpH, HDIM / 2,
        hp, HDIM, HDIM, 4,
        b_h2h, b_gen, nullptr, nullptr, out, nullptr, STEPS - 1);
}

// round 17
// speedup vs baseline: 1.2400x; 1.2400x over previous
#include <cuda_runtime.h>
#include <cuda_fp16.h>

#define BSZ   2048
#define TENC  32
#define DIN   512
#define HDIM  256
#define NCLS  38
#define STEPS 26   // MAXLEN+1
#define NHP   320  // hp(256) + probs(38) padded to 320
#define RS    20   // padded smem row stride in 32-bit words

// ---------------- scratch (device globals: allocation-free) ----------------
__device__ __align__(16) __half2 g_HprojH[(size_t)BSZ * TENC * HDIM / 2];  // 32 MB fp16
__device__ __align__(16) __half2 g_bhH[(size_t)BSZ * TENC * DIN / 2];      // 64 MB fp16
__device__ __align__(16) float    g_hp[BSZ * HDIM];
__device__ __align__(16) unsigned g_ctxH[BSZ * DIN / 2];                   // fp16 pairs
__device__ __align__(16) unsigned g_hH[2][BSZ * HDIM / 2];                 // fp16 pairs
__device__ __align__(16) float    g_c[BSZ * HDIM];
// packed fp16 B matrices (row = output col, K contiguous, 2 fp16 per word)
__device__ __align__(16) unsigned g_BpG[4 * HDIM * (DIN + HDIM) / 2];
__device__ __align__(16) unsigned g_BpH[NHP * HDIM / 2];
__device__ __align__(16) unsigned g_BpI[HDIM * DIN / 2];
__device__ __align__(16) float    g_biasG[4 * HDIM];

// ---------------- helpers ----------------
__device__ __forceinline__ unsigned pack_h2(float a, float b) {
    __half2 h = __floats2half2_rn(a, b);
    return *reinterpret_cast<unsigned*>(&h);
}
__device__ __forceinline__ float tanha(float x) {
    float y;
    asm("tanh.approx.f32 %0, %1;" : "=f"(y) : "f"(x));
    return y;
}
__device__ __forceinline__ void mma_f16(float* c, const unsigned* a, const unsigned* b) {
    asm volatile(
        "mma.sync.aligned.m16n8k16.row.col.f32.f16.f16.f32 "
        "{%0,%1,%2,%3},{%4,%5,%6,%7},{%8,%9},{%0,%1,%2,%3};"
        : "+f"(c[0]), "+f"(c[1]), "+f"(c[2]), "+f"(c[3])
        : "r"(a[0]), "r"(a[1]), "r"(a[2]), "r"(a[3]), "r"(b[0]), "r"(b[1]));
}
__device__ __forceinline__ void ldsm4(unsigned* r, unsigned addr) {
    asm volatile("ldmatrix.sync.aligned.m8n8.x4.shared.b16 {%0,%1,%2,%3}, [%4];"
                 : "=r"(r[0]), "=r"(r[1]), "=r"(r[2]), "=r"(r[3]) : "r"(addr));
}
__device__ __forceinline__ void cp16(unsigned saddr, const void* gptr) {
    asm volatile("cp.async.cg.shared.global [%0], [%1], 16;" :: "r"(saddr), "l"(gptr));
}
__device__ __forceinline__ void cp_commit() {
    asm volatile("cp.async.commit_group;" ::: "memory");
}
__device__ __forceinline__ void cp_wait1() {
    asm volatile("cp.async.wait_group 1;" ::: "memory");
}
__device__ __forceinline__ void cp_wait0() {
    asm volatile("cp.async.wait_group 0;" ::: "memory");
}

// ---------------- init: zero LSTM state, hp = b_h2h ----------------
__global__ void init_kernel(const float* __restrict__ b_h2h) {
    int i = blockIdx.x * blockDim.x + threadIdx.x;
    if (i < BSZ * HDIM) { g_c[i] = 0.f; g_hp[i] = b_h2h[i & (HDIM - 1)]; }
    if (i < BSZ * HDIM / 2) g_hH[0][i] = 0u;
}

// ---------------- convert batch_H -> fp16 (one-time) ----------------
__global__ void cvt_bh_kernel(const float4* __restrict__ in) {
    size_t i = (size_t)blockIdx.x * 256 + threadIdx.x;   // < 8M
    float4 v = in[i];
    g_bhH[2 * i]     = __float22half2_rn(make_float2(v.x, v.y));
    g_bhH[2 * i + 1] = __float22half2_rn(make_float2(v.z, v.w));
}

// ---------------- pack weights to fp16 pairs ----------------
// BpG packed row p (BN=128 blocks): blk=p>>7, q=p&127, wn=q>>5, gate=(q>>3)&3,
//   uu=q&7; unit = blk*32 + wn*8 + uu; orig n = gate*256 + unit
__global__ void pack_kernel(
    const float* __restrict__ W_ih, const float* __restrict__ W_hh,
    const float* __restrict__ W_h2h, const float* __restrict__ W_gen,
    const float* __restrict__ W_i2h,
    const float* __restrict__ b_ih, const float* __restrict__ b_hh)
{
    const int NG2 = 4 * HDIM * (DIN + HDIM) / 2;   // 393216
    const int NH2 = NHP * HDIM / 2;                // 40960
    const int NI2 = HDIM * DIN / 2;                // 65536
    int i = blockIdx.x * blockDim.x + threadIdx.x;
    if (i < NG2) {
        int p = i / 384, k = (i % 384) * 2;
        int blk = p >> 7, q = p & 127;
        int wn = q >> 5, gate = (q >> 3) & 3, uu = q & 7;
        int n = gate * 256 + blk * 32 + wn * 8 + uu;
        float v0, v1;
        if (k < DIN) {
            v0 = W_ih[(size_t)n * (DIN + NCLS) + k];
            v1 = W_ih[(size_t)n * (DIN + NCLS) + k + 1];
        } else {
            v0 = W_hh[(size_t)n * HDIM + (k - DIN)];
            v1 = W_hh[(size_t)n * HDIM + (k - DIN) + 1];
        }
        g_BpG[i] = pack_h2(v0, v1);
    } else if (i < NG2 + NH2) {
        int j = i - NG2;
        int n = j / 128, k = (j % 128) * 2;
        float v0 = 0.f, v1 = 0.f;
        if (n < HDIM) {
            v0 = W_h2h[(size_t)n * HDIM + k];
            v1 = W_h2h[(size_t)n * HDIM + k + 1];
        } else if (n < HDIM + NCLS) {
            v0 = W_gen[(size_t)(n - HDIM) * HDIM + k];
            v1 = W_gen[(size_t)(n - HDIM) * HDIM + k + 1];
        }
        g_BpH[j] = pack_h2(v0, v1);
    } else if (i < NG2 + NH2 + NI2) {
        int j = i - NG2 - NH2;
        g_BpI[j] = pack_h2(W_i2h[2 * j], W_i2h[2 * j + 1]);
    } else if (i < NG2 + NH2 + NI2 + 4 * HDIM) {
        int j = i - NG2 - NH2 - NI2;
        g_biasG[j] = b_ih[j] + b_hh[j];
    }
}

// ---------------- pipelined fp16 GEMM: out = A @ Bp^T (+epilogue) ----------
// Block: 2 m-warps x NW n-warps. Warp tile: (MT*16) x 32. BM=32*MT, BN=32*NW.
// 3-stage cp.async ring in dynamic smem; ldmatrix fragment loads.
// EPI 0: write fp16 pairs to ohw (H_proj).
// EPI 1: n<256 -> C=hp fp32 (+bias0); 256<=n<294 -> out2[...] (+bias1).
// EPI 2: fused LSTM -> update g_c (fp32), write h fp16 pairs to ohw.
template <int EPI, int NW, int MT>
__global__ void __launch_bounds__(64 * NW) gemm_f16(
    const unsigned* __restrict__ A0, int lda0,
    const unsigned* __restrict__ A1, int lda1, int KA,
    const unsigned* __restrict__ Bp, int ldb,
    float* __restrict__ C, int ldc, int K, int yoff,
    const float* __restrict__ bias0, const float* __restrict__ bias1,
    const float* __restrict__ Wih, const int* __restrict__ text,
    float* __restrict__ out2, unsigned* __restrict__ ohw, int step)
{
    constexpr int T  = 64 * NW;
    constexpr int BM = 32 * MT;
    constexpr int BN = 32 * NW;
    constexpr int AN = (2 * MT) / NW ? (2 * MT) / NW : 1;
    extern __shared__ unsigned sh[];
    unsigned* AsP = sh;
    unsigned* BsP = sh + 3 * BM * RS;
    const unsigned ABYTES = BM * RS * 4;
    const unsigned BBYTES = BN * RS * 4;

    const int tid  = threadIdx.x;
    const int lane = tid & 31;
    const int warp = tid >> 5;
    const int wm   = warp & 1;
    const int wn   = warp >> 1;
    const int g    = lane >> 2;
    const int ctg  = lane & 3;
    const int mBase = blockIdx.x * BM;
    const int nBase = (blockIdx.y + yoff) * BN;

    float acc[MT][4][4];
#pragma unroll
    for (int mt = 0; mt < MT; mt++)
#pragma unroll
        for (int nt = 0; nt < 4; nt++)
#pragma unroll
            for (int i = 0; i < 4; i++) acc[mt][nt][i] = 0.f;

    const int nk = K >> 5;

    const unsigned asBase = (unsigned)__cvta_generic_to_shared(AsP);
    const unsigned bsBase = (unsigned)__cvta_generic_to_shared(BsP);
    const int aRowL = wm * (MT * 16) + (lane & 7) + ((lane >> 3) & 1) * 8;
    const int aColL = (lane >> 4) * 4;
    const unsigned aAddr0 = asBase + (aRowL * RS + aColL) * 4;
    const int bRowL = wn * 32 + (lane >> 4) * 8 + (lane & 7);
    const int bColL = ((lane >> 3) & 1) * 4;
    const unsigned bAddr0 = bsBase + (bRowL * RS + bColL) * 4;

    auto cpasync_tile = [&](int kt, int st) {
        const int k0 = kt << 5;
        const unsigned* aS; int aLd, aOffW;
        if (k0 < KA) { aS = A0; aLd = lda0; aOffW = k0 >> 1; }
        else         { aS = A1; aLd = lda1; aOffW = (k0 - KA) >> 1; }
        const unsigned aDst = asBase + st * ABYTES;
        const unsigned bDst = bsBase + st * BBYTES;
#pragma unroll
        for (int t = 0; t < AN; t++) {
            int i = t * T + tid;
            int r = i >> 2, cg = i & 3;
            cp16(aDst + (r * RS + cg * 4) * 4,
                 aS + (size_t)(mBase + r) * aLd + aOffW + cg * 4);
        }
#pragma unroll
        for (int t = 0; t < 2; t++) {
            int i = t * T + tid;
            int r = i >> 2, cg = i & 3;
            cp16(bDst + (r * RS + cg * 4) * 4,
                 Bp + (size_t)(nBase + r) * ldb + (k0 >> 1) + cg * 4);
        }
    };

    cpasync_tile(0, 0);
    cp_commit();
    if (nk > 1) { cpasync_tile(1, 1); cp_commit(); }

    int cur = 0;
    for (int kt = 0; kt < nk; kt++) {
        if (kt + 1 < nk) cp_wait1(); else cp_wait0();
        __syncthreads();

        if (kt + 2 < nk) {
            int pf = cur + 2; if (pf >= 3) pf -= 3;
            cpasync_tile(kt + 2, pf);
            cp_commit();
        }

        const unsigned bufA = cur * ABYTES;
        const unsigned bufB = cur * BBYTES;
#pragma unroll
        for (int kk = 0; kk < 2; kk++) {       // two k16 halves of the 32-tile
            unsigned af[MT][4], bf[2][4];
#pragma unroll
            for (int mt = 0; mt < MT; mt++)
                ldsm4(af[mt], aAddr0 + bufA + (unsigned)(mt * 16 * RS * 4 + kk * 32));
#pragma unroll
            for (int p = 0; p < 2; p++)
                ldsm4(bf[p], bAddr0 + bufB + (unsigned)(p * 16 * RS * 4 + kk * 32));
#pragma unroll
            for (int mt = 0; mt < MT; mt++)
#pragma unroll
                for (int nt = 0; nt < 4; nt++)
                    mma_f16(acc[mt][nt], af[mt], &bf[nt >> 1][(nt & 1) * 2]);
        }

        cur = (cur == 2) ? 0 : cur + 1;
    }

    // ---- epilogue ----
    const int unit0 = blockIdx.y * 32 + wn * 8 + 2 * ctg;  // EPI 2 only (NW=4)
#pragma unroll
    for (int mt = 0; mt < MT; mt++) {
        int r0 = mBase + wm * (MT * 16) + mt * 16 + g;
        int r1 = r0 + 8;
        if (EPI == 0) {
#pragma unroll
            for (int nt = 0; nt < 4; nt++) {
                int c0 = nBase + wn * 32 + nt * 8 + 2 * ctg;
                ohw[((size_t)r0 * ldc + c0) >> 1] = pack_h2(acc[mt][nt][0], acc[mt][nt][1]);
                ohw[((size_t)r1 * ldc + c0) >> 1] = pack_h2(acc[mt][nt][2], acc[mt][nt][3]);
            }
        } else if (EPI == 1) {
#pragma unroll
            for (int nt = 0; nt < 4; nt++) {
                int c0 = nBase + wn * 32 + nt * 8 + 2 * ctg;
                if (c0 < HDIM) {
                    float b0 = bias0[c0], b1 = bias0[c0 + 1];
                    *reinterpret_cast<float2*>(C + (size_t)r0 * ldc + c0) =
                        make_float2(acc[mt][nt][0] + b0, acc[mt][nt][1] + b1);
                    *reinterpret_cast<float2*>(C + (size_t)r1 * ldc + c0) =
                        make_float2(acc[mt][nt][2] + b0, acc[mt][nt][3] + b1);
                } else if (c0 < HDIM + NCLS) {
                    int cc = c0 - HDIM;
                    float b0 = bias1[cc], b1 = bias1[cc + 1];
                    *reinterpret_cast<float2*>(
                        out2 + (size_t)r0 * (STEPS * NCLS) + step * NCLS + cc) =
                        make_float2(acc[mt][nt][0] + b0, acc[mt][nt][1] + b1);
                    *reinterpret_cast<float2*>(
                        out2 + (size_t)r1 * (STEPS * NCLS) + step * NCLS + cc) =
                        make_float2(acc[mt][nt][2] + b0, acc[mt][nt][3] + b1);
                }
            }
        } else {  // EPI == 2: fused LSTM (nt == gate)
            int chr0 = text[r0 * STEPS + step];
            int chr1 = text[r1 * STEPS + step];
            float gv0[4][2], gv1[4][2];
#pragma unroll
            for (int gate = 0; gate < 4; gate++) {
                int n0 = gate * 256 + unit0;
                float b0 = g_biasG[n0], b1 = g_biasG[n0 + 1];
                const float* w0 = Wih + (size_t)n0 * 550 + 512;
                const float* w1 = w0 + 550;
                gv0[gate][0] = acc[mt][gate][0] + b0 + w0[chr0];
                gv0[gate][1] = acc[mt][gate][1] + b1 + w1[chr0];
                gv1[gate][0] = acc[mt][gate][2] + b0 + w0[chr1];
                gv1[gate][1] = acc[mt][gate][3] + b1 + w1[chr1];
            }
            auto cell = [](float i_, float f_, float g_, float o_, float c_,
                           float& cn, float& hn) {
                float si = 1.f / (1.f + __expf(-i_));
                float sf = 1.f / (1.f + __expf(-f_));
                float so = 1.f / (1.f + __expf(-o_));
                cn = sf * c_ + si * tanhf(g_);
                hn = so * tanhf(cn);
            };
            float2 cold0 = *reinterpret_cast<float2*>(g_c + r0 * HDIM + unit0);
            float2 cold1 = *reinterpret_cast<float2*>(g_c + r1 * HDIM + unit0);
            float2 cn0, hn0, cn1, hn1;
            cell(gv0[0][0], gv0[1][0], gv0[2][0], gv0[3][0], cold0.x, cn0.x, hn0.x);
            cell(gv0[0][1], gv0[1][1], gv0[2][1], gv0[3][1], cold0.y, cn0.y, hn0.y);
            cell(gv1[0][0], gv1[1][0], gv1[2][0], gv1[3][0], cold1.x, cn1.x, hn1.x);
            cell(gv1[0][1], gv1[1][1], gv1[2][1], gv1[3][1], cold1.y, cn1.y, hn1.y);
            *reinterpret_cast<float2*>(g_c + r0 * HDIM + unit0) = cn0;
            *reinterpret_cast<float2*>(g_c + r1 * HDIM + unit0) = cn1;
            ohw[(r0 * HDIM + unit0) >> 1] = pack_h2(hn0.x, hn0.y);
            ohw[(r1 * HDIM + unit0) >> 1] = pack_h2(hn1.x, hn1.y);
        }
    }
}

// ---------------- attention: fp16 H_proj + fp16 batch_H, fp16 ctx out ------
__global__ void __launch_bounds__(256) attn_kernel(const float* __restrict__ Wscore)
{
    const int b = blockIdx.x;
    const int tid = threadIdx.x;
    __shared__ float2 hp2[128];
    __shared__ float2 w2[128];
    __shared__ float e_s[TENC];

    if (tid < 128) {
        hp2[tid] = reinterpret_cast<const float2*>(g_hp + b * HDIM)[tid];
        w2[tid]  = reinterpret_cast<const float2*>(Wscore)[tid];
    }
    __syncthreads();

    const int w = tid >> 5, lane = tid & 31;
#pragma unroll
    for (int tt = 0; tt < 4; tt++) {
        int t = tt * 8 + w;
        const __half2* row = g_HprojH + ((size_t)b * TENC + t) * (HDIM / 2);
        float s = 0.f;
#pragma unroll
        for (int j = 0; j < 4; j++) {
            int idx = lane + 32 * j;
            float2 r = __half22float2(row[idx]);
            float2 hh = hp2[idx];
            float2 ww = w2[idx];
            s += ww.x * tanha(r.x + hh.x) + ww.y * tanha(r.y + hh.y);
        }
#pragma unroll
        for (int o = 16; o; o >>= 1) s += __shfl_xor_sync(0xffffffffu, s, o);
        if (lane == 0) e_s[t] = s;
    }
    __syncthreads();

    if (tid < 32) {
        float v = e_s[tid];
        float m = v;
#pragma unroll
        for (int o = 16; o; o >>= 1) m = fmaxf(m, __shfl_xor_sync(0xffffffffu, m, o));
        float p = __expf(v - m);
        float ss = p;
#pragma unroll
        for (int o = 16; o; o >>= 1) ss += __shfl_xor_sync(0xffffffffu, ss, o);
        e_s[tid] = p / ss;
    }
    __syncthreads();

    float ax = 0.f, ay = 0.f;
    const __half2* bh2 = g_bhH + (size_t)b * TENC * (DIN / 2);
#pragma unroll
    for (int t = 0; t < TENC; t++) {
        float al = e_s[t];
        float2 v = __half22float2(bh2[t * (DIN / 2) + tid]);
        ax += al * v.x;
        ay += al * v.y;
    }
    g_ctxH[b * (DIN / 2) + tid] = pack_h2(ax, ay);
}

// ---------------- launch ----------------
extern "C" void kernel_launch(void* const* d_in, const int* in_sizes, int n_in,
                              void* d_out, int out_size)
{
    const float* batchH  = (const float*)d_in[0];
    const int*   text    = (const int*)d_in[1];
    const float* W_i2h   = (const float*)d_in[2];
    const float* W_h2h   = (const float*)d_in[3];
    const float* b_h2h   = (const float*)d_in[4];
    const float* W_score = (const float*)d_in[5];
    const float* W_ih    = (const float*)d_in[6];
    const float* b_ih    = (const float*)d_in[7];
    const float* W_hh    = (const float*)d_in[8];
    const float* b_hh    = (const float*)d_in[9];
    const float* W_gen   = (const float*)d_in[10];
    const float* b_gen   = (const float*)d_in[11];
    float*       out     = (float*)d_out;

    float *hp;
    unsigned *ctxH, *h0, *h1, *bpG, *bpH, *bpI, *hprojW, *bhW;
    cudaGetSymbolAddress((void**)&hprojW, g_HprojH);
    cudaGetSymbolAddress((void**)&bhW,    g_bhH);
    cudaGetSymbolAddress((void**)&hp,     g_hp);
    cudaGetSymbolAddress((void**)&ctxH,   g_ctxH);
    cudaGetSymbolAddress((void**)&h0,     g_hH);
    h1 = h0 + BSZ * HDIM / 2;
    cudaGetSymbolAddress((void**)&bpG,    g_BpG);
    cudaGetSymbolAddress((void**)&bpH,    g_BpH);
    cudaGetSymbolAddress((void**)&bpI,    g_BpI);

    // dynamic smem: 3 stages x (A BM*RS + B BN*RS) words
    const int SM44 = 3 * (128 * RS + 128 * RS) * 4;  // H_proj MT=4: 61440 B
    const int SM42 = 3 * (64 * RS + 128 * RS) * 4;   // gates MT=2:  46080 B
    const int SM22 = 3 * (64 * RS + 64 * RS) * 4;    // hp/tail:     30720 B
    static int configured = 0;
    if (!configured) {
        cudaFuncSetAttribute((const void*)gemm_f16<0, 4, 4>,
                             cudaFuncAttributeMaxDynamicSharedMemorySize, SM44);
        cudaFuncSetAttribute((const void*)gemm_f16<2, 4, 2>,
                             cudaFuncAttributeMaxDynamicSharedMemorySize, SM42);
        cudaFuncSetAttribute((const void*)gemm_f16<1, 2, 2>,
                             cudaFuncAttributeMaxDynamicSharedMemorySize, SM22);
        configured = 1;
    }

    init_kernel<<<(BSZ * HDIM) / 256, 256>>>(b_h2h);
    const int packN = 4 * HDIM * (DIN + HDIM) / 2 + NHP * HDIM / 2 + HDIM * DIN / 2 + 4 * HDIM;
    pack_kernel<<<(packN + 255) / 256, 256>>>(W_ih, W_hh, W_h2h, W_gen, W_i2h, b_ih, b_hh);
    cvt_bh_kernel<<<(BSZ * TENC * DIN / 4) / 256, 256>>>((const float4*)batchH);

    // H_proj (fp16 in/out): M=65536, N=256, K=512; BM=128, BN=128 -> (512,2)
    gemm_f16<0, 4, 4><<<dim3(512, 2), 256, SM44>>>(
        bhW, DIN / 2, nullptr, 0, DIN,
        bpI, DIN / 2,
        nullptr, HDIM, DIN, 0,
        nullptr, nullptr, nullptr, nullptr, nullptr, hprojW, 0);

    for (int s = 0; s < STEPS; s++) {
        unsigned* hR = (s & 1) ? h1 : h0;
        unsigned* hW = (s & 1) ? h0 : h1;
        if (s > 0) {
            // hp_s = h @ W_h2h^T + b_h2h  AND  probs_{s-1} = h @ W_gen^T + b_gen
            gemm_f16<1, 2, 2><<<dim3(32, 5), 128, SM22>>>(
                hR, HDIM / 2, nullptr, 0, HDIM,
                bpH, HDIM / 2,
                hp, HDIM, HDIM, 0,
                b_h2h, b_gen, nullptr, nullptr, out, nullptr, s - 1);
        }
        attn_kernel<<<BSZ, 256>>>(W_score);
        // gates + fused LSTM: [ctx|h] @ BpG^T ; BM=64, BN=128 -> grid (32,8)
        gemm_f16<2, 4, 2><<<dim3(32, 8), 256, SM42>>>(
            ctxH, DIN / 2, hR, HDIM / 2, DIN,
            bpG, (DIN + HDIM) / 2,
            nullptr, 0, DIN + HDIM, 0,
            nullptr, nullptr, W_ih, text, nullptr, hW, s);
    }
    // probs for the final step (step 25 wrote h0)
    gemm_f16<1, 2, 2><<<dim3(32, 1), 128, SM22>>>(
        h0, HDIM / 2, nullptr, 0, HDIM,
        bpH, HDIM / 2,
        hp, HDIM, HDIM, 4,
        b_h2h, b_gen, nullptr, nullptr, out, nullptr, STEPS - 1);
}